// round 10
// baseline (speedup 1.0000x reference)
#include <cuda_runtime.h>
#include <math.h>

#define Nn 4096
#define Dd 256
#define Ss 32
#define Kk 4
#define KS 128           // K*S combined column dim
#define MAXNBR 256
#define ETA 0.5f

// ---- static device scratch (no allocations allowed) ----
__device__ int   g_cnt[Nn];
__device__ int   g_nbr[Nn][MAXNBR];      // 4 MB
__device__ float g_Z2[Nn][KS];           // 2 MB   Z[i][k*32+s]
__device__ float g_G2[Nn][KS];           // 2 MB
__device__ float g_Ut[KS][Dd];           // 128 KB U viewed [ks][d] (finalize)
__device__ float g_orth[16];

__device__ __constant__ int c_pk[10] = {0,0,0,0,1,1,1,2,2,3};
__device__ __constant__ int c_pl[10] = {0,1,2,3,1,2,3,2,3,3};

static __device__ __forceinline__ void fma4(float4& a, const float4& u, float g) {
    a.x += u.x * g; a.y += u.y * g; a.z += u.z * g; a.w += u.w * g;
}

// ===========================================================================
// Launch 1 (fused), 778 blocks x 256:
//   [0,512)   build_adj   (DRAM-bound mask scan)
//   [512,640) compute_Z   (FMA-bound, reads original U layout)
//   [640,768) Ut transpose
//   [768,778) orth_pair   (reads U directly -> independent of transpose)
// All four groups are mutually independent.
// ===========================================================================
__global__ void fused_prep(const float* __restrict__ mask,
                           const float* __restrict__ H,
                           const float* __restrict__ U) {
    __shared__ __align__(16) char sbuf[34 * 1024 + 64];
    int b = blockIdx.x;
    int t = threadIdx.x;

    if (b < 512) {
        // ---- build_adj: 1 warp per row, float4 + 4 ballots ----
        int warp = t >> 5, lane = t & 31;
        int row  = b * 8 + warp;
        const float4* m4 = (const float4*)(mask + (size_t)row * Nn);
        unsigned lt = (1u << lane) - 1u;
        int base = 0;
#pragma unroll 2
        for (int c = 0; c < Nn / 4; c += 32) {
            float4 v = __ldcs(&m4[c + lane]);
            int e0 = (c + lane) * 4;
            bool p; unsigned bb;
            p = v.x > 0.5f; bb = __ballot_sync(0xffffffffu, p);
            if (p) { int pos = base + __popc(bb & lt); if (pos < MAXNBR) g_nbr[row][pos] = e0 + 0; }
            base += __popc(bb);
            p = v.y > 0.5f; bb = __ballot_sync(0xffffffffu, p);
            if (p) { int pos = base + __popc(bb & lt); if (pos < MAXNBR) g_nbr[row][pos] = e0 + 1; }
            base += __popc(bb);
            p = v.z > 0.5f; bb = __ballot_sync(0xffffffffu, p);
            if (p) { int pos = base + __popc(bb & lt); if (pos < MAXNBR) g_nbr[row][pos] = e0 + 2; }
            base += __popc(bb);
            p = v.w > 0.5f; bb = __ballot_sync(0xffffffffu, p);
            if (p) { int pos = base + __popc(bb & lt); if (pos < MAXNBR) g_nbr[row][pos] = e0 + 3; }
            base += __popc(bb);
        }
        if (lane == 0) g_cnt[row] = (base < MAXNBR) ? base : MAXNBR;
    } else if (b < 640) {
        // ---- compute_Z: Z2[i][ks] = sum_d H[i][d] * U[k][d][s] ----
        float (*Hs)[Dd] = (float (*)[Dd])sbuf;       // 32 KB
        int i0 = (b - 512) * 32;
        const float4* Hf4 = (const float4*)H;
        float4* Hs4 = (float4*)&Hs[0][0];
#pragma unroll
        for (int q = 0; q < 8; q++)
            Hs4[q * 256 + t] = Hf4[(size_t)i0 * 64 + q * 256 + t];
        __syncthreads();

        int tx = t & 31, ty = t >> 5;                // tx: ks4 group, ty: 8 row-groups
        int k = tx >> 3, s4 = tx & 7;
        const float4* Up = (const float4*)(U + ((size_t)k * Dd) * Ss + s4 * 4);
        int r0 = ty * 4;
        float4 a0 = {0,0,0,0}, a1 = {0,0,0,0}, a2 = {0,0,0,0}, a3 = {0,0,0,0};
#pragma unroll 4
        for (int d = 0; d < Dd; d++) {
            float4 u = Up[d * 8];                    // stride Ss floats = 8 float4
            fma4(a0, u, Hs[r0 + 0][d]);
            fma4(a1, u, Hs[r0 + 1][d]);
            fma4(a2, u, Hs[r0 + 2][d]);
            fma4(a3, u, Hs[r0 + 3][d]);
        }
        float4* Z4 = (float4*)&g_Z2[0][0];
        Z4[(size_t)(i0 + r0 + 0) * 32 + tx] = a0;
        Z4[(size_t)(i0 + r0 + 1) * 32 + tx] = a1;
        Z4[(size_t)(i0 + r0 + 2) * 32 + tx] = a2;
        Z4[(size_t)(i0 + r0 + 3) * 32 + tx] = a3;
    } else if (b < 768) {
        // ---- transpose U -> Ut[ks][d] ----
        int idx = (b - 640) * 256 + t;               // 32768 elems
        int k = idx >> 13;
        int r = idx & 8191;
        int d = r >> 5;
        int s = r & 31;
        g_Ut[k * Ss + s][d] = U[idx];
    } else {
        // ---- orth_pair p: gram block, reads U directly (coalesced) ----
        float (*As)[129] = (float (*)[129])sbuf;                 // 16.5 KB
        float (*Bs)[129] = (float (*)[129])(sbuf + 16512);       // 16.5 KB
        float* red       = (float*)(sbuf + 33024);               // 1 KB
        int p = b - 768;
        int k = c_pk[p], l = c_pl[p];
        int ga = t >> 4, gb = t & 15;
        int a0 = ga * 2, b0 = gb * 2;
        float c00 = 0, c01 = 0, c10 = 0, c11 = 0;

        const float* Uk = U + (size_t)k * Dd * Ss;
        const float* Ul = U + (size_t)l * Dd * Ss;
        for (int d0 = 0; d0 < Dd; d0 += 128) {
            __syncthreads();
            // d-major load order: 32-float contiguous rows (coalesced),
            // smem write conflict-free via 129 pad
            for (int idx = t; idx < 32 * 128; idx += 256) {
                int d = idx >> 5, a = idx & 31;
                As[a][d] = Uk[(size_t)(d0 + d) * Ss + a];
                Bs[a][d] = Ul[(size_t)(d0 + d) * Ss + a];
            }
            __syncthreads();
#pragma unroll 4
            for (int d = 0; d < 128; d++) {
                float av0 = As[a0][d], av1 = As[a0 + 1][d];
                float bv0 = Bs[b0][d], bv1 = Bs[b0 + 1][d];
                c00 += av0 * bv0; c01 += av0 * bv1;
                c10 += av1 * bv0; c11 += av1 * bv1;
            }
        }

        float local;
        if (k == l) {
            float e;
            local = 0.f;
            e = c00 - ((a0     == b0    ) ? 1.f : 0.f); local += e * e;
            e = c01 - ((a0     == b0 + 1) ? 1.f : 0.f); local += e * e;
            e = c10 - ((a0 + 1 == b0    ) ? 1.f : 0.f); local += e * e;
            e = c11 - ((a0 + 1 == b0 + 1) ? 1.f : 0.f); local += e * e;
        } else {
            local = c00 * c00 + c01 * c01 + c10 * c10 + c11 * c11;
        }
        red[t] = local;
        __syncthreads();
        for (int o = 128; o; o >>= 1) {
            if (t < o) red[t] += red[t + o];
            __syncthreads();
        }
        if (t == 0) g_orth[p] = red[0];
    }
}

// ===========================================================================
// Launch 2: sparse attention, online softmax, double-buffered full-tile
// prefetch (8 x LDG.128/lane). Block Nn (if present) sums the orth partials.
// ===========================================================================
__global__ void attn(const float* __restrict__ lp, float* __restrict__ loss_out) {
    __shared__ int   snbr[MAXNBR];
    __shared__ float Zt[Kk][32][33];                 // 33-pad: conflict-free both axes
    __shared__ float ew[Kk][32];
    __shared__ float zq[Kk][Ss];
    __shared__ int   scnt;

    int i = blockIdx.x;
    if (i >= Nn) {                                   // orth final sum (1 block)
        if (threadIdx.x == 0) {
            float s = 0.f;
            for (int p = 0; p < 10; p++) s += g_orth[p];
            loss_out[0] = s;
        }
        return;
    }

    int t = threadIdx.x;
    int k = t >> 5, lane = t & 31;

    if (t == 0) scnt = g_cnt[i];
    zq[k][lane] = g_Z2[i][t] * __expf(lp[t]);        // t == k*32+lane
    // zero-init this warp's tile (stale smem must be finite for 0-weight FMAs)
    for (int j = lane; j < 32 * 33; j += 32) (&Zt[k][0][0])[j] = 0.f;
    __syncthreads();
    int cnt = scnt;
    for (int j = t; j < cnt; j += 128) snbr[j] = g_nbr[i][j];
    __syncthreads();

    const float inv = 0.17677669529663687f;          // 1/sqrt(32)
    int kbase = k << 5;
    int jj = lane >> 3;                              // row-group base 0..3
    int cc = (lane & 7) * 4;                         // float4 chunk 0..28
    float M = -3.0e38f, L = 0.f;
    float a0 = 0.f, a1 = 0.f, a2 = 0.f, a3 = 0.f;

    // prefetch tile 0 into registers (8 x LDG.128 per lane = full 32x32 tile)
    float4 pv[8];
#pragma unroll
    for (int it = 0; it < 8; it++) {
        int r = jj + 4 * it;
        if (r < cnt) pv[it] = *(const float4*)&g_Z2[snbr[r]][kbase + cc];
    }

    for (int t0 = 0; t0 < cnt; t0 += 32) {
        int tl = min(32, cnt - t0);

        // commit prefetched tile to smem
#pragma unroll
        for (int it = 0; it < 8; it++) {
            int r = jj + 4 * it;
            if (r < tl) {
                Zt[k][r][cc + 0] = pv[it].x; Zt[k][r][cc + 1] = pv[it].y;
                Zt[k][r][cc + 2] = pv[it].z; Zt[k][r][cc + 3] = pv[it].w;
            }
        }
        __syncwarp();

        // prefetch NEXT tile (overlaps with compute below)
        int n0 = t0 + 32;
        if (n0 < cnt) {
#pragma unroll
            for (int it = 0; it < 8; it++) {
                int r = n0 + jj + 4 * it;
                if (r < cnt) pv[it] = *(const float4*)&g_Z2[snbr[r]][kbase + cc];
            }
        }

        // scores: lane = neighbor in tile (2 partial sums break the FFMA chain)
        float s0 = 0.f, s1 = 0.f;
#pragma unroll
        for (int s = 0; s < Ss; s += 2) {
            s0 += zq[k][s]     * Zt[k][lane][s];
            s1 += zq[k][s + 1] * Zt[k][lane][s + 1];
        }
        float sc = (lane < tl) ? (s0 + s1) * inv : -3.0e38f;

        float mt = sc;
#pragma unroll
        for (int o = 16; o; o >>= 1) mt = fmaxf(mt, __shfl_xor_sync(0xffffffffu, mt, o));
        float newM = fmaxf(M, mt);
        float e = (lane < tl) ? __expf(sc - newM) : 0.f;
        ew[k][lane] = e;
        float es = e;
#pragma unroll
        for (int o = 16; o; o >>= 1) es += __shfl_xor_sync(0xffffffffu, es, o);
        float scale = __expf(M - newM);              // first tile: underflows to 0
        L = L * scale + es;
        a0 *= scale; a1 *= scale; a2 *= scale; a3 *= scale;
        M = newM;
        __syncwarp();

        // accumulate: lane = channel s; full 32 (ew is 0 beyond tl, Zt finite)
#pragma unroll
        for (int j = 0; j < 32; j += 4) {
            a0 += ew[k][j + 0] * Zt[k][j + 0][lane];
            a1 += ew[k][j + 1] * Zt[k][j + 1][lane];
            a2 += ew[k][j + 2] * Zt[k][j + 2][lane];
            a3 += ew[k][j + 3] * Zt[k][j + 3][lane];
        }
        __syncwarp();                                // before next tile overwrite
    }
    g_G2[i][t] = ((a0 + a1) + (a2 + a3)) / L;
}

// ===========================================================================
// Launch 3: finalize only. out = softthresh(H + ETA * G2 @ Ut, thr)
// ===========================================================================
__global__ void finalize(const float* __restrict__ H, const float* __restrict__ thr,
                         float* __restrict__ out) {
    __shared__ float Gs[32][KS];                     // 16 KB
    int b = blockIdx.x;
    int t = threadIdx.x;
    int i0 = b * 32;
    const float4* Gf4 = (const float4*)&g_G2[0][0];
    float4* Gs4 = (float4*)&Gs[0][0];
#pragma unroll
    for (int q = 0; q < 4; q++)
        Gs4[q * 256 + t] = Gf4[(size_t)i0 * 32 + q * 256 + t];
    __syncthreads();

    int tx = t & 63, ty = t >> 6;
    int r0 = ty * 8;
    float4 acc[8];
#pragma unroll
    for (int r = 0; r < 8; r++) acc[r] = make_float4(0, 0, 0, 0);

#pragma unroll 2
    for (int ks = 0; ks < KS; ks++) {
        float4 u = *(const float4*)&g_Ut[ks][tx * 4];
#pragma unroll
        for (int r = 0; r < 8; r++) fma4(acc[r], u, Gs[r0 + r][ks]);
    }

    const float4* Hf4 = (const float4*)H;
    const float4* Tf4 = (const float4*)thr;
    float4* Of4 = (float4*)out;
    float4 th = Tf4[tx];
#pragma unroll
    for (int r = 0; r < 8; r++) {
        int i = i0 + r0 + r;
        float4 h = Hf4[(size_t)i * 64 + tx];
        float4 v;
        v.x = h.x + ETA * acc[r].x;
        v.y = h.y + ETA * acc[r].y;
        v.z = h.z + ETA * acc[r].z;
        v.w = h.w + ETA * acc[r].w;
        float m;
        m = fmaxf(fabsf(v.x) - th.x, 0.f); v.x = copysignf(m, v.x);
        m = fmaxf(fabsf(v.y) - th.y, 0.f); v.y = copysignf(m, v.y);
        m = fmaxf(fabsf(v.z) - th.z, 0.f); v.z = copysignf(m, v.z);
        m = fmaxf(fabsf(v.w) - th.w, 0.f); v.w = copysignf(m, v.w);
        Of4[(size_t)i * 64 + tx] = v;
    }
}

// ---------------------------------------------------------------------------
extern "C" void kernel_launch(void* const* d_in, const int* in_sizes, int n_in,
                              void* d_out, int out_size) {
    const float* H    = (const float*)d_in[0];   // [N, D]
    const float* mask = (const float*)d_in[1];   // [N, N]
    const float* U    = (const float*)d_in[2];   // [K, D, S]
    const float* lp   = (const float*)d_in[3];   // [K, S]
    const float* thr  = (const float*)d_in[4];   // [D]
    float* out = (float*)d_out;

    bool want_loss = (out_size > Nn * Dd);
    fused_prep<<<778, 256>>>(mask, H, U);
    attn<<<want_loss ? Nn + 1 : Nn, 128>>>(lp, out + (size_t)Nn * Dd);
    finalize<<<128, 256>>>(H, thr, out);
}

// round 11
// speedup vs baseline: 1.3286x; 1.3286x over previous
#include <cuda_runtime.h>
#include <math.h>

#define Nn 4096
#define Dd 256
#define Ss 32
#define Kk 4
#define KS 128           // K*S combined column dim
#define MAXNBR 256
#define ETA 0.5f

// ---- static device scratch (no allocations allowed) ----
__device__ int   g_cnt[Nn];
__device__ int   g_nbr[Nn][MAXNBR];      // 4 MB
__device__ float g_Z2[Nn][KS];           // 2 MB   Z[i][k*32+s]
__device__ float g_G2[Nn][KS];           // 2 MB
__device__ float g_Ut[KS][Dd];           // 128 KB U viewed [ks][d] (finalize)
__device__ float g_orth[16];

__device__ __constant__ int c_pk[10] = {0,0,0,0,1,1,1,2,2,3};
__device__ __constant__ int c_pl[10] = {0,1,2,3,1,2,3,2,3,3};

static __device__ __forceinline__ void fma4(float4& a, const float4& u, float g) {
    a.x += u.x * g; a.y += u.y * g; a.z += u.z * g; a.w += u.w * g;
}

// ===========================================================================
// Launch 1 (fused), 778 blocks x 256:
//   [0,512)   build_adj   (ballot-free: lane-local masks + shfl prefix scan)
//   [512,640) compute_Z   (FMA-bound, reads original U layout)
//   [640,768) Ut transpose
//   [768,778) orth_pair   (reads U directly; 64-wide d-tiles keep smem small)
// All four groups are mutually independent. Union smem = 32 KB.
// ===========================================================================
__global__ void fused_prep(const float* __restrict__ mask,
                           const float* __restrict__ H,
                           const float* __restrict__ U) {
    __shared__ __align__(16) char sbuf[32 * 1024];
    int b = blockIdx.x;
    int t = threadIdx.x;

    if (b < 512) {
        // ---- build_adj: 1 warp per row. Lane owns contiguous 32 columns per
        // 1024-column chunk: 8 independent LDG.128 (MLP=8) -> 32-bit local
        // mask -> warp prefix scan -> sorted writes. No ballots.
        int warp = t >> 5, lane = t & 31;
        int row  = b * 8 + warp;
        const float4* m4 = (const float4*)(mask + (size_t)row * Nn);
        int base = 0;
#pragma unroll
        for (int c = 0; c < 4; c++) {                // 4 chunks of 1024 cols
            float4 v[8];
#pragma unroll
            for (int q = 0; q < 8; q++)
                v[q] = __ldcs(&m4[c * 256 + lane * 8 + q]);
            unsigned msk = 0;
#pragma unroll
            for (int q = 0; q < 8; q++) {
                if (v[q].x > 0.5f) msk |= 1u << (q * 4 + 0);
                if (v[q].y > 0.5f) msk |= 1u << (q * 4 + 1);
                if (v[q].z > 0.5f) msk |= 1u << (q * 4 + 2);
                if (v[q].w > 0.5f) msk |= 1u << (q * 4 + 3);
            }
            int cnt = __popc(msk);
            int pre = cnt;                           // inclusive scan
#pragma unroll
            for (int o = 1; o < 32; o <<= 1) {
                int nb = __shfl_up_sync(0xffffffffu, pre, o);
                if (lane >= o) pre += nb;
            }
            int pos  = base + pre - cnt;             // exclusive offset
            int col0 = c * 1024 + lane * 32;
            unsigned m = msk;
            while (m) {
                int bit = __ffs(m) - 1;
                m &= m - 1;
                if (pos < MAXNBR) g_nbr[row][pos] = col0 + bit;
                pos++;
            }
            base += __shfl_sync(0xffffffffu, pre, 31);
        }
        if (lane == 0) g_cnt[row] = (base < MAXNBR) ? base : MAXNBR;
    } else if (b < 640) {
        // ---- compute_Z: Z2[i][ks] = sum_d H[i][d] * U[k][d][s] ----
        float (*Hs)[Dd] = (float (*)[Dd])sbuf;       // 32 KB
        int i0 = (b - 512) * 32;
        const float4* Hf4 = (const float4*)H;
        float4* Hs4 = (float4*)&Hs[0][0];
#pragma unroll
        for (int q = 0; q < 8; q++)
            Hs4[q * 256 + t] = Hf4[(size_t)i0 * 64 + q * 256 + t];
        __syncthreads();

        int tx = t & 31, ty = t >> 5;                // tx: ks4 group, ty: 8 row-groups
        int k = tx >> 3, s4 = tx & 7;
        const float4* Up = (const float4*)(U + ((size_t)k * Dd) * Ss + s4 * 4);
        int r0 = ty * 4;
        float4 a0 = {0,0,0,0}, a1 = {0,0,0,0}, a2 = {0,0,0,0}, a3 = {0,0,0,0};
#pragma unroll 4
        for (int d = 0; d < Dd; d++) {
            float4 u = Up[d * 8];                    // stride Ss floats = 8 float4
            fma4(a0, u, Hs[r0 + 0][d]);
            fma4(a1, u, Hs[r0 + 1][d]);
            fma4(a2, u, Hs[r0 + 2][d]);
            fma4(a3, u, Hs[r0 + 3][d]);
        }
        float4* Z4 = (float4*)&g_Z2[0][0];
        Z4[(size_t)(i0 + r0 + 0) * 32 + tx] = a0;
        Z4[(size_t)(i0 + r0 + 1) * 32 + tx] = a1;
        Z4[(size_t)(i0 + r0 + 2) * 32 + tx] = a2;
        Z4[(size_t)(i0 + r0 + 3) * 32 + tx] = a3;
    } else if (b < 768) {
        // ---- transpose U -> Ut[ks][d] ----
        int idx = (b - 640) * 256 + t;               // 32768 elems
        int k = idx >> 13;
        int r = idx & 8191;
        int d = r >> 5;
        int s = r & 31;
        g_Ut[k * Ss + s][d] = U[idx];
    } else {
        // ---- orth_pair p: gram block, 64-wide d-tiles (17.7 KB smem) ----
        float (*As)[65] = (float (*)[65])sbuf;                   // 8320 B
        float (*Bs)[65] = (float (*)[65])(sbuf + 8320);          // 8320 B
        float* red      = (float*)(sbuf + 16640);                // 1 KB
        int p = b - 768;
        int k = c_pk[p], l = c_pl[p];
        int ga = t >> 4, gb = t & 15;
        int a0 = ga * 2, b0 = gb * 2;
        float c00 = 0, c01 = 0, c10 = 0, c11 = 0;

        const float* Uk = U + (size_t)k * Dd * Ss;
        const float* Ul = U + (size_t)l * Dd * Ss;
        for (int d0 = 0; d0 < Dd; d0 += 64) {
            __syncthreads();
            // d-major load order: contiguous 32-float rows (coalesced),
            // smem writes conflict-free via 65 pad
            for (int idx = t; idx < 32 * 64; idx += 256) {
                int d = idx >> 5, a = idx & 31;
                As[a][d] = Uk[(size_t)(d0 + d) * Ss + a];
                Bs[a][d] = Ul[(size_t)(d0 + d) * Ss + a];
            }
            __syncthreads();
#pragma unroll 4
            for (int d = 0; d < 64; d++) {
                float av0 = As[a0][d], av1 = As[a0 + 1][d];
                float bv0 = Bs[b0][d], bv1 = Bs[b0 + 1][d];
                c00 += av0 * bv0; c01 += av0 * bv1;
                c10 += av1 * bv0; c11 += av1 * bv1;
            }
        }

        float local;
        if (k == l) {
            float e;
            local = 0.f;
            e = c00 - ((a0     == b0    ) ? 1.f : 0.f); local += e * e;
            e = c01 - ((a0     == b0 + 1) ? 1.f : 0.f); local += e * e;
            e = c10 - ((a0 + 1 == b0    ) ? 1.f : 0.f); local += e * e;
            e = c11 - ((a0 + 1 == b0 + 1) ? 1.f : 0.f); local += e * e;
        } else {
            local = c00 * c00 + c01 * c01 + c10 * c10 + c11 * c11;
        }
        red[t] = local;
        __syncthreads();
        for (int o = 128; o; o >>= 1) {
            if (t < o) red[t] += red[t + o];
            __syncthreads();
        }
        if (t == 0) g_orth[p] = red[0];
    }
}

// ===========================================================================
// Launch 2: sparse attention, online softmax, double-buffered full-tile
// prefetch (8 x LDG.128/lane). Block Nn (if present) sums the orth partials.
// ===========================================================================
__global__ void attn(const float* __restrict__ lp, float* __restrict__ loss_out) {
    __shared__ int   snbr[MAXNBR];
    __shared__ float Zt[Kk][32][33];                 // 33-pad: conflict-free both axes
    __shared__ float ew[Kk][32];
    __shared__ float zq[Kk][Ss];
    __shared__ int   scnt;

    int i = blockIdx.x;
    if (i >= Nn) {                                   // orth final sum (1 block)
        if (threadIdx.x == 0) {
            float s = 0.f;
            for (int p = 0; p < 10; p++) s += g_orth[p];
            loss_out[0] = s;
        }
        return;
    }

    int t = threadIdx.x;
    int k = t >> 5, lane = t & 31;

    if (t == 0) scnt = g_cnt[i];
    zq[k][lane] = g_Z2[i][t] * __expf(lp[t]);        // t == k*32+lane
    // zero-init this warp's tile (stale smem must be finite for 0-weight FMAs)
    for (int j = lane; j < 32 * 33; j += 32) (&Zt[k][0][0])[j] = 0.f;
    __syncthreads();
    int cnt = scnt;
    for (int j = t; j < cnt; j += 128) snbr[j] = g_nbr[i][j];
    __syncthreads();

    const float inv = 0.17677669529663687f;          // 1/sqrt(32)
    int kbase = k << 5;
    int jj = lane >> 3;                              // row-group base 0..3
    int cc = (lane & 7) * 4;                         // float4 chunk 0..28
    float M = -3.0e38f, L = 0.f;
    float a0 = 0.f, a1 = 0.f, a2 = 0.f, a3 = 0.f;

    // prefetch tile 0 into registers (8 x LDG.128 per lane = full 32x32 tile)
    float4 pv[8];
#pragma unroll
    for (int it = 0; it < 8; it++) {
        int r = jj + 4 * it;
        if (r < cnt) pv[it] = *(const float4*)&g_Z2[snbr[r]][kbase + cc];
    }

    for (int t0 = 0; t0 < cnt; t0 += 32) {
        int tl = min(32, cnt - t0);

        // commit prefetched tile to smem
#pragma unroll
        for (int it = 0; it < 8; it++) {
            int r = jj + 4 * it;
            if (r < tl) {
                Zt[k][r][cc + 0] = pv[it].x; Zt[k][r][cc + 1] = pv[it].y;
                Zt[k][r][cc + 2] = pv[it].z; Zt[k][r][cc + 3] = pv[it].w;
            }
        }
        __syncwarp();

        // prefetch NEXT tile (overlaps with compute below)
        int n0 = t0 + 32;
        if (n0 < cnt) {
#pragma unroll
            for (int it = 0; it < 8; it++) {
                int r = n0 + jj + 4 * it;
                if (r < cnt) pv[it] = *(const float4*)&g_Z2[snbr[r]][kbase + cc];
            }
        }

        // scores: lane = neighbor in tile (2 partial sums break the FFMA chain)
        float s0 = 0.f, s1 = 0.f;
#pragma unroll
        for (int s = 0; s < Ss; s += 2) {
            s0 += zq[k][s]     * Zt[k][lane][s];
            s1 += zq[k][s + 1] * Zt[k][lane][s + 1];
        }
        float sc = (lane < tl) ? (s0 + s1) * inv : -3.0e38f;

        float mt = sc;
#pragma unroll
        for (int o = 16; o; o >>= 1) mt = fmaxf(mt, __shfl_xor_sync(0xffffffffu, mt, o));
        float newM = fmaxf(M, mt);
        float e = (lane < tl) ? __expf(sc - newM) : 0.f;
        ew[k][lane] = e;
        float es = e;
#pragma unroll
        for (int o = 16; o; o >>= 1) es += __shfl_xor_sync(0xffffffffu, es, o);
        float scale = __expf(M - newM);              // first tile: underflows to 0
        L = L * scale + es;
        a0 *= scale; a1 *= scale; a2 *= scale; a3 *= scale;
        M = newM;
        __syncwarp();

        // accumulate: lane = channel s; full 32 (ew is 0 beyond tl, Zt finite)
#pragma unroll
        for (int j = 0; j < 32; j += 4) {
            a0 += ew[k][j + 0] * Zt[k][j + 0][lane];
            a1 += ew[k][j + 1] * Zt[k][j + 1][lane];
            a2 += ew[k][j + 2] * Zt[k][j + 2][lane];
            a3 += ew[k][j + 3] * Zt[k][j + 3][lane];
        }
        __syncwarp();                                // before next tile overwrite
    }
    g_G2[i][t] = ((a0 + a1) + (a2 + a3)) / L;
}

// ===========================================================================
// Launch 3: finalize. out = softthresh(H + ETA * G2 @ Ut, thr)
// ===========================================================================
__global__ void finalize(const float* __restrict__ H, const float* __restrict__ thr,
                         float* __restrict__ out) {
    __shared__ float Gs[32][KS];                     // 16 KB
    int b = blockIdx.x;
    int t = threadIdx.x;
    int i0 = b * 32;
    const float4* Gf4 = (const float4*)&g_G2[0][0];
    float4* Gs4 = (float4*)&Gs[0][0];
#pragma unroll
    for (int q = 0; q < 4; q++)
        Gs4[q * 256 + t] = Gf4[(size_t)i0 * 32 + q * 256 + t];
    __syncthreads();

    int tx = t & 63, ty = t >> 6;
    int r0 = ty * 8;
    float4 acc[8];
#pragma unroll
    for (int r = 0; r < 8; r++) acc[r] = make_float4(0, 0, 0, 0);

#pragma unroll 2
    for (int ks = 0; ks < KS; ks++) {
        float4 u = *(const float4*)&g_Ut[ks][tx * 4];
#pragma unroll
        for (int r = 0; r < 8; r++) fma4(acc[r], u, Gs[r0 + r][ks]);
    }

    const float4* Hf4 = (const float4*)H;
    const float4* Tf4 = (const float4*)thr;
    float4* Of4 = (float4*)out;
    float4 th = Tf4[tx];
#pragma unroll
    for (int r = 0; r < 8; r++) {
        int i = i0 + r0 + r;
        float4 h = Hf4[(size_t)i * 64 + tx];
        float4 v;
        v.x = h.x + ETA * acc[r].x;
        v.y = h.y + ETA * acc[r].y;
        v.z = h.z + ETA * acc[r].z;
        v.w = h.w + ETA * acc[r].w;
        float m;
        m = fmaxf(fabsf(v.x) - th.x, 0.f); v.x = copysignf(m, v.x);
        m = fmaxf(fabsf(v.y) - th.y, 0.f); v.y = copysignf(m, v.y);
        m = fmaxf(fabsf(v.z) - th.z, 0.f); v.z = copysignf(m, v.z);
        m = fmaxf(fabsf(v.w) - th.w, 0.f); v.w = copysignf(m, v.w);
        Of4[(size_t)i * 64 + tx] = v;
    }
}

// ---------------------------------------------------------------------------
extern "C" void kernel_launch(void* const* d_in, const int* in_sizes, int n_in,
                              void* d_out, int out_size) {
    const float* H    = (const float*)d_in[0];   // [N, D]
    const float* mask = (const float*)d_in[1];   // [N, N]
    const float* U    = (const float*)d_in[2];   // [K, D, S]
    const float* lp   = (const float*)d_in[3];   // [K, S]
    const float* thr  = (const float*)d_in[4];   // [D]
    float* out = (float*)d_out;

    bool want_loss = (out_size > Nn * Dd);
    fused_prep<<<778, 256>>>(mask, H, U);
    attn<<<want_loss ? Nn + 1 : Nn, 128>>>(lp, out + (size_t)Nn * Dd);
    finalize<<<128, 256>>>(H, thr, out);
}